// round 16
// baseline (speedup 1.0000x reference)
#include <cuda_runtime.h>
#include <cuda_fp16.h>
#include <math.h>
#include <stdint.h>

#define NN 4096
#define EE 32768
#define EC 32768         // single chunk: 1 gemm + 1 msg launch per layer
#define NCHUNK (EE / EC)
#define BBATCH 16
#define LL 4

#define SQ3C     1.73205080757f
#define SQ5C     2.23606797750f
#define INV_SQ3  0.57735026919f
#define INV_SQ5  0.44721359550f
#define INV_SQ75 0.36514837167f
#define A0C      0.13363062095f
#define A1C      0.20412414523f
#define A2C      0.27950849719f
#define ISQ32    0.17677669530f
#define ISQ16    0.25f
#define ISQ8     0.35355339059f
#define RBFN     0.79788458f

// k_setup block ranges: geom, W3 permute, node init, CG
#define SB_GEOM 128
#define SB_PREP (SB_GEOM + 3456)
#define SB_NODE (SB_PREP + NN)
#define SB_TOTAL (SB_NODE + 1)

__constant__ float cQ[5][9] = {
    {0.f, 0.f, 0.86602540378f,  0.f, 0.f, 0.f,  0.86602540378f, 0.f, 0.f},
    {0.f, 0.86602540378f, 0.f,  0.86602540378f, 0.f, 0.f,  0.f, 0.f, 0.f},
    {-0.5f, 0.f, 0.f,  0.f, 1.f, 0.f,  0.f, 0.f, -0.5f},
    {0.f, 0.f, 0.f,  0.f, 0.f, 0.86602540378f,  0.f, 0.86602540378f, 0.f},
    {-0.86602540378f, 0.f, 0.f,  0.f, 0.f, 0.f,  0.f, 0.f, 0.86602540378f}};

__constant__ int segOff[12] = {0, 1024, 1536, 1792, 2304, 2560, 2816, 2944, 3200, 3328, 3392, 3456};
__constant__ int segU[11]   = {32, 16, 8, 32, 16, 16, 8, 32, 16, 8, 8};
__constant__ int segV[11]   = {32, 32, 32, 16, 16, 16, 16, 8, 8, 8, 8};

__device__ float  g_s1[EE * 3];
__device__ float  g_s2[EE * 5];
__device__ float  g_rbf[EE * 8];
__device__ __half g_hidh[EE * 64];
__device__ __half g_w3h[(size_t)LL * 64 * 3456];   // permuted fp16 W3
__device__ float  g_b3p[LL * 3456];                // permuted bias
__device__ __half g_wh[(size_t)EC * 3456];         // 226 MB fp16
__device__ float  g_h0[2][NN * 32];
__device__ float  g_h1[2][NN * 48];
__device__ float  g_h2[2][NN * 40];
__device__ float  g_agg0[NN * 32];
__device__ float  g_agg1[NN * 48];
__device__ float  g_agg2[NN * 40];
__device__ float  g_att[NN];
__device__ float  g_pool[BBATCH * 32];
__device__ float  g_C222[125];

__device__ __forceinline__ float siluf(float x) { return x / (1.f + expf(-x)); }

#define LDSM_X4(r0, r1, r2, r3, addr)                                              \
    asm volatile("ldmatrix.sync.aligned.m8n8.x4.shared.b16 {%0,%1,%2,%3}, [%4];"   \
                 : "=r"(r0), "=r"(r1), "=r"(r2), "=r"(r3) : "r"(addr))
#define LDSM_X4_T(r0, r1, r2, r3, addr)                                                 \
    asm volatile("ldmatrix.sync.aligned.m8n8.x4.trans.shared.b16 {%0,%1,%2,%3}, [%4];"  \
                 : "=r"(r0), "=r"(r1), "=r"(r2), "=r"(r3) : "r"(addr))
#define MMA_F16(d, a, b0, b1)                                                      \
    asm volatile("mma.sync.aligned.m16n8k16.row.col.f32.f16.f16.f32 "              \
                 "{%0,%1,%2,%3}, {%4,%5,%6,%7}, {%8,%9}, {%0,%1,%2,%3};"           \
                 : "+f"(d[0]), "+f"(d[1]), "+f"(d[2]), "+f"(d[3])                  \
                 : "r"(a[0]), "r"(a[1]), "r"(a[2]), "r"(a[3]), "r"(b0), "r"(b1))

// ---------------- fused setup: edge geom + W3 permute + embed/zero + CG ----------------
__global__ void k_setup(const float* __restrict__ pos, const int* __restrict__ ei,
                        const float* __restrict__ W3, const float* __restrict__ b3,
                        const float* __restrict__ x, const float* __restrict__ embW) {
    int b = blockIdx.x, t = threadIdx.x;
    if (b < SB_GEOM) {
        int e = b * 256 + t;
        int s = ei[e], d = ei[EE + e];
        float rx = pos[d * 3 + 0] - pos[s * 3 + 0];
        float ry = pos[d * 3 + 1] - pos[s * 3 + 1];
        float rz = pos[d * 3 + 2] - pos[s * 3 + 2];
        float dist = sqrtf(rx * rx + ry * ry + rz * rz);
        dist = fmaxf(dist, 1e-6f);
        float nx = rx / dist, ny = ry / dist, nz = rz / dist;
        g_s1[e * 3 + 0] = SQ3C * nx;
        g_s1[e * 3 + 1] = SQ3C * ny;
        g_s1[e * 3 + 2] = SQ3C * nz;
        g_s2[e * 5 + 0] = SQ5C * (SQ3C * nx * nz);
        g_s2[e * 5 + 1] = SQ5C * (SQ3C * nx * ny);
        g_s2[e * 5 + 2] = SQ5C * (ny * ny - 0.5f * (nx * nx + nz * nz));
        g_s2[e * 5 + 3] = SQ5C * (SQ3C * ny * nz);
        g_s2[e * 5 + 4] = SQ5C * (0.5f * SQ3C * (nz * nz - nx * nx));
#pragma unroll
        for (int i = 0; i < 8; i++) {
            float c = 6.f * (float)i / 7.f;
            float tt = dist - c;
            g_rbf[e * 8 + i] = expf(-2.f * tt * tt) * RBFN;
        }
    } else if (b < SB_PREP) {
        int idx = (b - SB_GEOM) * 256 + t;   // LL*64*3456 exactly
        int l = idx / (64 * 3456);
        int rem = idx % (64 * 3456);
        int k = rem / 3456;
        int cp = rem % 3456;
        int seg = 0;
        while (cp >= segOff[seg + 1]) seg++;
        int local = cp - segOff[seg];
        int U = segU[seg], V = segV[seg];
        int v = local / U, u = local % U;
        int c = segOff[seg] + u * V + v;
        g_w3h[idx] = __float2half(W3[(size_t)l * 221184 + (size_t)k * 3456 + c]);
        if (k == 0) g_b3p[l * 3456 + cp] = b3[l * 3456 + c];
    } else if (b < SB_NODE) {
        int n = b - SB_PREP;
        __shared__ float xr[64];
        if (t < 64) xr[t] = x[n * 64 + t];
        __syncthreads();
        if (t < 32) {
            float s = 0.f;
#pragma unroll 8
            for (int c = 0; c < 64; c++) s += xr[c] * embW[c * 32 + t];
            g_h0[0][n * 32 + t] = s * 0.125f;
            g_agg0[n * 32 + t] = 0.f;
        }
        if (t < 48) { g_h1[0][n * 48 + t] = 0.f; g_agg1[n * 48 + t] = 0.f; }
        if (t < 40) { g_h2[0][n * 40 + t] = 0.f; g_agg2[n * 40 + t] = 0.f; }
    } else {
        __shared__ float T[256];
        __shared__ float red[256];
        float v = 0.f;
        if (t < 125) {
            int i = t / 25, j = (t / 5) % 5, k = t % 5;
            for (int a = 0; a < 3; a++)
                for (int bb = 0; bb < 3; bb++)
                    for (int c = 0; c < 3; c++)
                        v += cQ[i][a * 3 + bb] * cQ[j][bb * 3 + c] * cQ[k][c * 3 + a];
        }
        T[t] = v;
        red[t] = v * v;
        __syncthreads();
        for (int s = 128; s > 0; s >>= 1) {
            if (t < s) red[t] += red[t + s];
            __syncthreads();
        }
        float inv = rsqrtf(red[0]);
        if (t < 125) g_C222[t] = T[t] * inv;
    }
}

// ---------------- radial MLP (fp16 output) — unchanged ----------------
__global__ void k_radial(const float* __restrict__ W1, const float* __restrict__ b1,
                         const float* __restrict__ W2, const float* __restrict__ b2) {
    int le = threadIdx.x >> 6;
    int t = threadIdx.x & 63;
    int e = blockIdx.x * 4 + le;
    __shared__ __align__(16) float sh[4][64];
    const float* r = g_rbf + e * 8;
    float z = b1[t];
#pragma unroll
    for (int i = 0; i < 8; i++) z += r[i] * W1[i * 64 + t];
    sh[le][t] = siluf(z);
    __syncthreads();
    float z2 = b2[t];
    const float4* s4 = (const float4*)sh[le];
#pragma unroll
    for (int i = 0; i < 16; i++) {
        float4 a = s4[i];
        z2 += a.x * W2[(i * 4 + 0) * 64 + t];
        z2 += a.y * W2[(i * 4 + 1) * 64 + t];
        z2 += a.z * W2[(i * 4 + 2) * 64 + t];
        z2 += a.w * W2[(i * 4 + 3) * 64 + t];
    }
    g_hidh[e * 64 + t] = __float2half(siluf(z2));
}

// ---------------- fp16 GEMM: 128x128 tile, forced 4 blocks/SM ----------------
__global__ void __launch_bounds__(256, 4) k_gemm_h(int chunk, int l) {
    __shared__ __align__(16) __half As[128 * 64];
    __shared__ __align__(16) __half Bs[64 * 128];
    int bx = blockIdx.x, by = blockIdx.y;
    int tid = threadIdx.x;
    const __half* Bm = g_w3h + (size_t)l * 221184;
    const float* bias = g_b3p + l * 3456;

    {
        int row = tid >> 1;
        int cq0 = (tid & 1) * 4;
        const uint4* src = (const uint4*)(g_hidh + (size_t)(chunk * EC + by * 128 + row) * 64);
#pragma unroll
        for (int q = 0; q < 4; q++) {
            int ck = cq0 + q;
            *(uint4*)&As[row * 64 + ((ck ^ (row & 7)) * 8)] = src[ck];
        }
    }
    {
        int k = tid >> 2;
        int bq0 = (tid & 3) * 4;
        const uint4* src = (const uint4*)(Bm + (size_t)k * 3456 + bx * 128);
#pragma unroll
        for (int q = 0; q < 4; q++) {
            int ck = bq0 + q;
            *(uint4*)&Bs[k * 128 + ((ck ^ (k & 7)) * 8)] = src[ck];
        }
    }
    __syncthreads();

    int lane = tid & 31, w = tid >> 5;
    int wr = w & 3, wc = w >> 2;
    int off = lane & 7, qd = lane >> 3;
    int rowSel = ((qd & 1) << 3) + off;
    int chkSel = qd >> 1;

    uint32_t aBase = (uint32_t)__cvta_generic_to_shared(As);
    uint32_t bBase = (uint32_t)__cvta_generic_to_shared(Bs);

    float acc[2][8][4];
#pragma unroll
    for (int mi = 0; mi < 2; mi++)
#pragma unroll
        for (int n8 = 0; n8 < 8; n8++)
#pragma unroll
            for (int q = 0; q < 4; q++) acc[mi][n8][q] = 0.f;

#pragma unroll
    for (int kk = 0; kk < 4; kk++) {
        uint32_t a[2][4];
#pragma unroll
        for (int mi = 0; mi < 2; mi++) {
            int row = wr * 32 + mi * 16 + rowSel;
            int chk = kk * 2 + chkSel;
            uint32_t ad = aBase + (uint32_t)(row * 64 + ((chk ^ (row & 7)) * 8)) * 2;
            LDSM_X4(a[mi][0], a[mi][1], a[mi][2], a[mi][3], ad);
        }
        int krow = kk * 16 + rowSel;
        int ksw = krow & 7;
        uint32_t b[4][4];
#pragma unroll
        for (int j = 0; j < 4; j++) {
            int chk = wc * 8 + j * 2 + chkSel;
            uint32_t bd = bBase + (uint32_t)(krow * 128 + ((chk ^ ksw) * 8)) * 2;
            LDSM_X4_T(b[j][0], b[j][1], b[j][2], b[j][3], bd);
        }
#pragma unroll
        for (int mi = 0; mi < 2; mi++)
#pragma unroll
            for (int j = 0; j < 4; j++) {
                MMA_F16(acc[mi][j * 2 + 0], a[mi], b[j][0], b[j][1]);
                MMA_F16(acc[mi][j * 2 + 1], a[mi], b[j][2], b[j][3]);
            }
    }

    int g = lane >> 2, t4 = lane & 3;
#pragma unroll
    for (int n8 = 0; n8 < 8; n8++) {
        int c = bx * 128 + wc * 64 + n8 * 8 + 2 * t4;
        float2 bv = *(const float2*)(bias + c);
#pragma unroll
        for (int mi = 0; mi < 2; mi++) {
            int r = by * 128 + wr * 32 + mi * 16 + g;
            *(__half2*)(g_wh + (size_t)r * 3456 + c) =
                __floats2half2_rn(acc[mi][n8][0] + bv.x, acc[mi][n8][1] + bv.y);
            *(__half2*)(g_wh + (size_t)(r + 8) * 3456 + c) =
                __floats2half2_rn(acc[mi][n8][2] + bv.x, acc[mi][n8][3] + bv.y);
        }
    }
}

// ---------------- message kernel: 2 edges per warp, convergent m1/m2 — unchanged ----------------
__global__ void __launch_bounds__(256) k_msg(int cur, int e0, const int* __restrict__ ei) {
    __shared__ float S[16][400];
    int wid = threadIdx.x >> 5, lane = threadIdx.x & 31;
    int eA = e0 + (blockIdx.x * 8 + wid) * 2;
    int eB = eA + 1;
    float* PA = S[wid * 2];
    float* PB = S[wid * 2 + 1];
    int srcA = ei[eA], dstA = ei[EE + eA];
    int srcB = ei[eB], dstB = ei[EE + eB];
    const float* h0 = g_h0[cur];
    const float* h1 = g_h1[cur];
    const float* h2 = g_h2[cur];
    const __half* wpA = g_wh + (size_t)(eA - e0) * 3456;
    const __half* wpB = g_wh + (size_t)(eB - e0) * 3456;

#pragma unroll
    for (int h = 0; h < 2; h++) {
        float* P = h ? PB : PA;
        int e = h ? eB : eA;
        int src = h ? srcB : srcA;

        P[lane] = h0[src * 32 + lane];
        for (int i = lane; i < 48; i += 32) P[32 + i] = h1[src * 48 + i];
        for (int i = lane; i < 40; i += 32) P[80 + i] = h2[src * 40 + i];
        if (lane < 3) P[336 + lane] = g_s1[e * 3 + lane];
        if (lane < 5) P[339 + lane] = g_s2[e * 5 + lane];
        __syncwarp();

        if (lane < 9) {
            int i = lane / 3, j = lane % 3;
            float s = 0.f;
#pragma unroll
            for (int k = 0; k < 5; k++) s += P[339 + k] * cQ[k][i * 3 + j];
            P[344 + lane] = s;
        } else if (lane < 24) {
            int idx = lane - 9;
            int a = idx / 3, c = idx % 3;
            float s = 0.f;
#pragma unroll
            for (int b = 0; b < 3; b++) s += cQ[a][b * 3 + c] * P[336 + b];
            P[353 + idx] = s;
        } else {
            int u = lane - 24;
            float s = 0.f;
#pragma unroll
            for (int k = 0; k < 5; k++) s += P[80 + u * 5 + k] * P[339 + k];
            P[136 + u] = s * INV_SQ5;
        }
        __syncwarp();
        if (lane < 25) {
            int a = lane / 5, k = lane % 5;
            float s = 0.f;
#pragma unroll
            for (int b = 0; b < 5; b++) s += P[339 + b] * g_C222[(a * 5 + b) * 5 + k];
            P[368 + lane] = s;
        } else {
            int u = lane - 25;
            float s = 0.f;
#pragma unroll
            for (int i = 0; i < 3; i++) s += P[32 + u * 3 + i] * P[336 + i];
            P[120 + u] = s * INV_SQ3;
        }
        __syncwarp();
        if (lane < 9) {
            int u = lane + 7;
            float s = 0.f;
#pragma unroll
            for (int i = 0; i < 3; i++) s += P[32 + u * 3 + i] * P[336 + i];
            P[120 + u] = s * INV_SQ3;
        }
        __syncwarp();

        for (int idx = lane; idx < 192; idx += 32) {
            if (idx < 48) {
                int u = idx / 3, j = idx % 3;
                float s = 0.f;
#pragma unroll
                for (int i = 0; i < 3; i++) s += P[32 + u * 3 + i] * P[344 + i * 3 + j];
                P[144 + idx] = s * INV_SQ75;
            } else if (idx < 72) {
                int t = idx - 48;
                int u = t / 3, c = t % 3;
                float s = 0.f;
#pragma unroll
                for (int a = 0; a < 5; a++) s += P[80 + u * 5 + a] * P[353 + a * 3 + c];
                P[192 + t] = s * INV_SQ75;
            } else if (idx < 152) {
                int t = idx - 72;
                int u = t / 5, k = t % 5;
                float s = 0.f;
#pragma unroll
                for (int i = 0; i < 3; i++) s += P[32 + u * 3 + i] * P[353 + k * 3 + i];
                P[216 + t] = s * INV_SQ75;
            } else {
                int t = idx - 152;
                int u = t / 5, k = t % 5;
                float s = 0.f;
#pragma unroll
                for (int a = 0; a < 5; a++) s += P[80 + u * 5 + a] * P[368 + a * 5 + k];
                P[296 + t] = s;
            }
        }
        __syncwarp();
    }

#pragma unroll
    for (int h = 0; h < 2; h++) {
        float* P = h ? PB : PA;
        const __half* wp = h ? wpB : wpA;
        int dst = h ? dstB : dstA;
        int v = lane;
        float acc = 0.f;
        const uint4* q0 = (const uint4*)(wp + v * 32);
#pragma unroll
        for (int b = 0; b < 4; b++) {
            uint4 x = q0[b];
            const __half2* hh = (const __half2*)&x;
#pragma unroll
            for (int i = 0; i < 4; i++) {
                float2 f = __half22float2(hh[i]);
                int u = b * 8 + i * 2;
                acc += f.x * P[u] + f.y * P[u + 1];
            }
        }
        const uint4* q1 = (const uint4*)(wp + 1024 + v * 16);
#pragma unroll
        for (int b = 0; b < 2; b++) {
            uint4 x = q1[b];
            const __half2* hh = (const __half2*)&x;
#pragma unroll
            for (int i = 0; i < 4; i++) {
                float2 f = __half22float2(hh[i]);
                int u = b * 8 + i * 2;
                acc += f.x * P[120 + u] + f.y * P[120 + u + 1];
            }
        }
        {
            uint4 x = *(const uint4*)(wp + 1536 + v * 8);
            const __half2* hh = (const __half2*)&x;
#pragma unroll
            for (int i = 0; i < 4; i++) {
                float2 f = __half22float2(hh[i]);
                int u = i * 2;
                acc += f.x * P[136 + u] + f.y * P[136 + u + 1];
            }
        }
        atomicAdd(&g_agg0[dst * 32 + v], A0C * acc);
    }

    {
        int h = lane >> 4;
        int v = lane & 15;
        float* P = h ? PB : PA;
        const __half* wp = h ? wpB : wpA;
        int dst = h ? dstB : dstA;

        float p011 = 0.f;
        const uint4* q0 = (const uint4*)(wp + 1792 + v * 32);
#pragma unroll
        for (int b = 0; b < 4; b++) {
            uint4 x = q0[b];
            const __half2* hh = (const __half2*)&x;
#pragma unroll
            for (int i = 0; i < 4; i++) {
                float2 f = __half22float2(hh[i]);
                int u = b * 8 + i * 2;
                p011 += f.x * P[u] + f.y * P[u + 1];
            }
        }
        float a1c[3] = {0.f, 0.f, 0.f};
        float b1c[3] = {0.f, 0.f, 0.f};
        const uint4* qa = (const uint4*)(wp + 2304 + v * 16);
#pragma unroll
        for (int b = 0; b < 2; b++) {
            uint4 x = qa[b];
            const __half2* hh = (const __half2*)&x;
#pragma unroll
            for (int i = 0; i < 4; i++) {
                float2 f = __half22float2(hh[i]);
                int u = b * 8 + i * 2;
#pragma unroll
                for (int j = 0; j < 3; j++)
                    a1c[j] += f.x * P[32 + u * 3 + j] + f.y * P[32 + (u + 1) * 3 + j];
            }
        }
        const uint4* qb = (const uint4*)(wp + 2560 + v * 16);
#pragma unroll
        for (int b = 0; b < 2; b++) {
            uint4 x = qb[b];
            const __half2* hh = (const __half2*)&x;
#pragma unroll
            for (int i = 0; i < 4; i++) {
                float2 f = __half22float2(hh[i]);
                int u = b * 8 + i * 2;
#pragma unroll
                for (int j = 0; j < 3; j++)
                    b1c[j] += f.x * P[144 + u * 3 + j] + f.y * P[144 + (u + 1) * 3 + j];
            }
        }
        {
            uint4 x = *(const uint4*)(wp + 2816 + v * 8);
            const __half2* hh = (const __half2*)&x;
#pragma unroll
            for (int i = 0; i < 4; i++) {
                float2 f = __half22float2(hh[i]);
                int u = i * 2;
#pragma unroll
                for (int j = 0; j < 3; j++)
                    b1c[j] += f.x * P[192 + u * 3 + j] + f.y * P[192 + (u + 1) * 3 + j];
            }
        }
#pragma unroll
        for (int j = 0; j < 3; j++) {
            float m = A1C * ((p011 * P[336 + j] + a1c[j]) * INV_SQ3 + b1c[j]);
            atomicAdd(&g_agg1[dst * 48 + v * 3 + j], m);
        }
    }

    if (lane < 16) {
        int h = lane >> 3;
        int v = lane & 7;
        float* P = h ? PB : PA;
        const __half* wp = h ? wpB : wpA;
        int dst = h ? dstB : dstA;

        float p022 = 0.f;
        const uint4* q0 = (const uint4*)(wp + 2944 + v * 32);
#pragma unroll
        for (int b = 0; b < 4; b++) {
            uint4 x = q0[b];
            const __half2* hh = (const __half2*)&x;
#pragma unroll
            for (int i = 0; i < 4; i++) {
                float2 f = __half22float2(hh[i]);
                int u = b * 8 + i * 2;
                p022 += f.x * P[u] + f.y * P[u + 1];
            }
        }
        float t2c[5] = {0.f, 0.f, 0.f, 0.f, 0.f};
        const uint4* qa = (const uint4*)(wp + 3200 + v * 16);
#pragma unroll
        for (int b = 0; b < 2; b++) {
            uint4 x = qa[b];
            const __half2* hh = (const __half2*)&x;
#pragma unroll
            for (int i = 0; i < 4; i++) {
                float2 f = __half22float2(hh[i]);
                int u = b * 8 + i * 2;
#pragma unroll
                for (int k = 0; k < 5; k++)
                    t2c[k] += f.x * P[216 + u * 5 + k] + f.y * P[216 + (u + 1) * 5 + k];
            }
        }
        {
            uint4 x = *(const uint4*)(wp + 3328 + v * 8);
            const __half2* hh = (const __half2*)&x;
#pragma unroll
            for (int i = 0; i < 4; i++) {
                float2 f = __half22float2(hh[i]);
                int u = i * 2;
#pragma unroll
                for (int k = 0; k < 5; k++)
                    t2c[k] += (f.x * P[80 + u * 5 + k] + f.y * P[80 + (u + 1) * 5 + k]) * INV_SQ5;
            }
        }
        {
            uint4 x = *(const uint4*)(wp + 3392 + v * 8);
            const __half2* hh = (const __half2*)&x;
#pragma unroll
            for (int i = 0; i < 4; i++) {
                float2 f = __half22float2(hh[i]);
                int u = i * 2;
#pragma unroll
                for (int k = 0; k < 5; k++)
                    t2c[k] += f.x * P[296 + u * 5 + k] + f.y * P[296 + (u + 1) * 5 + k];
            }
        }
#pragma unroll
        for (int k = 0; k < 5; k++) {
            float m = A2C * (p022 * P[339 + k] * INV_SQ5 + t2c[k]);
            atomicAdd(&g_agg2[dst * 40 + v * 5 + k], m);
        }
    }
}

// ---------------- self interaction + aggregate, rezero agg — unchanged ----------------
__global__ void k_si(int cur, const float* __restrict__ siW0, const float* __restrict__ siW1,
                     const float* __restrict__ siW2) {
    int n = blockIdx.x, t = threadIdx.x;
    int nxt = cur ^ 1;
    __shared__ float o0[32], o1[48], o2[40];
    if (t < 32) o0[t] = g_h0[cur][n * 32 + t];
    else if (t < 80) o1[t - 32] = g_h1[cur][n * 48 + (t - 32)];
    else if (t < 120) o2[t - 80] = g_h2[cur][n * 40 + (t - 80)];
    __syncthreads();
    if (t < 32) {
        float s = 0.f;
#pragma unroll 8
        for (int u = 0; u < 32; u++) s += o0[u] * siW0[u * 32 + t];
        g_h0[nxt][n * 32 + t] = s * ISQ32 + g_agg0[n * 32 + t];
        g_agg0[n * 32 + t] = 0.f;
    } else if (t < 80) {
        int idx = t - 32;
        int v = idx / 3, i = idx % 3;
        float s = 0.f;
#pragma unroll 4
        for (int u = 0; u < 16; u++) s += o1[u * 3 + i] * siW1[u * 16 + v];
        g_h1[nxt][n * 48 + idx] = s * ISQ16 + g_agg1[n * 48 + idx];
        g_agg1[n * 48 + idx] = 0.f;
    } else if (t < 120) {
        int idx = t - 80;
        int v = idx / 5, k = idx % 5;
        float s = 0.f;
#pragma unroll
        for (int u = 0; u < 8; u++) s += o2[u * 5 + k] * siW2[u * 8 + v];
        g_h2[nxt][n * 40 + idx] = s * ISQ8 + g_agg2[n * 40 + idx];
        g_agg2[n * 40 + idx] = 0.f;
    }
}

// ---------------- attention MLP: 8 nodes per block — unchanged ----------------
__global__ void k_attmlp(const float* __restrict__ W1, const float* __restrict__ b1,
                         const float* __restrict__ W2, const float* __restrict__ b2,
                         const float* __restrict__ W3, const float* __restrict__ b3) {
    int n0 = blockIdx.x * 8;
    int t = threadIdx.x;
    __shared__ float hr[8][32];
    __shared__ float a1[8][128];
    __shared__ float red[128];
    for (int i = t; i < 256; i += 128)
        hr[i >> 5][i & 31] = g_h0[0][(n0 + (i >> 5)) * 32 + (i & 31)];
    __syncthreads();
    float z[8];
    float bb = b1[t];
#pragma unroll
    for (int n = 0; n < 8; n++) z[n] = bb;
    for (int c = 0; c < 32; c++) {
        float wv = W1[c * 128 + t];
#pragma unroll
        for (int n = 0; n < 8; n++) z[n] += hr[n][c] * wv;
    }
#pragma unroll
    for (int n = 0; n < 8; n++) a1[n][t] = siluf(z[n]);
    __syncthreads();
    float z2[8];
    float bb2 = b2[t];
#pragma unroll
    for (int n = 0; n < 8; n++) z2[n] = bb2;
    for (int c = 0; c < 128; c++) {
        float wv = W2[c * 128 + t];
#pragma unroll
        for (int n = 0; n < 8; n++) z2[n] += a1[n][c] * wv;
    }
    float w3 = W3[t];
    float b3v = b3[0];
    for (int n = 0; n < 8; n++) {
        red[t] = siluf(z2[n]) * w3;
        __syncthreads();
        for (int s = 64; s > 0; s >>= 1) {
            if (t < s) red[t] += red[t + s];
            __syncthreads();
        }
        if (t == 0) g_att[n0 + n] = red[0] + b3v;
        __syncthreads();
    }
}

// ---------------- pooling — unchanged ----------------
__global__ void k_pool(const int* __restrict__ batch) {
    int b = blockIdx.x, tid = threadIdx.x;
    int lane = tid & 31;
    __shared__ float red[256];
    __shared__ float gacc[32];
    __shared__ float s_amax, s_den;
    float lm = -1e30f;
    for (int n = tid; n < NN; n += 256)
        if (batch[n] == b) lm = fmaxf(lm, g_att[n]);
    red[tid] = lm;
    __syncthreads();
    for (int s = 128; s > 0; s >>= 1) {
        if (tid < s) red[tid] = fmaxf(red[tid], red[tid + s]);
        __syncthreads();
    }
    if (tid == 0) s_amax = red[0];
    if (tid < 32) gacc[tid] = 0.f;
    __syncthreads();
    float amax = s_amax;
    float lden = 0.f;
    float acc[32];
#pragma unroll
    for (int c = 0; c < 32; c++) acc[c] = 0.f;
    for (int n = tid; n < NN; n += 256)
        if (batch[n] == b) {
            float ex = expf(g_att[n] - amax);
            lden += ex;
#pragma unroll
            for (int c = 0; c < 32; c++) acc[c] += ex * g_h0[0][n * 32 + c];
        }
#pragma unroll
    for (int c = 0; c < 32; c++) {
        float v = acc[c];
#pragma unroll
        for (int o = 16; o > 0; o >>= 1) v += __shfl_xor_sync(0xffffffff, v, o);
        if (lane == 0) atomicAdd(&gacc[c], v);
    }
    red[tid] = lden;
    __syncthreads();
    for (int s = 128; s > 0; s >>= 1) {
        if (tid < s) red[tid] += red[tid + s];
        __syncthreads();
    }
    if (tid == 0) s_den = red[0];
    __syncthreads();
    if (tid < 32) g_pool[b * 32 + tid] = gacc[tid] / s_den;
}

// ---------------- final linear + layernorm — unchanged ----------------
__global__ void k_out(const float* __restrict__ W, const float* __restrict__ bo,
                      const float* __restrict__ lg, const float* __restrict__ lb,
                      float* __restrict__ out) {
    int b = blockIdx.x, j = threadIdx.x;
    __shared__ float gr[32];
    __shared__ float red[512];
    if (j < 32) gr[j] = g_pool[b * 32 + j];
    __syncthreads();
    float o = bo[j];
#pragma unroll 8
    for (int c = 0; c < 32; c++) o += gr[c] * W[c * 512 + j];
    red[j] = o;
    __syncthreads();
    for (int s = 256; s > 0; s >>= 1) {
        if (j < s) red[j] += red[j + s];
        __syncthreads();
    }
    float mu = red[0] / 512.f;
    __syncthreads();
    float d = o - mu;
    red[j] = d * d;
    __syncthreads();
    for (int s = 256; s > 0; s >>= 1) {
        if (j < s) red[j] += red[j + s];
        __syncthreads();
    }
    float var = red[0] / 512.f;
    out[b * 512 + j] = d * rsqrtf(var + 1e-5f) * lg[j] + lb[j];
}

extern "C" void kernel_launch(void* const* d_in, const int* in_sizes, int n_in,
                              void* d_out, int out_size) {
    const float* x      = (const float*)d_in[0];
    const float* pos    = (const float*)d_in[1];
    const float* emb_W  = (const float*)d_in[2];
    const float* si_W0  = (const float*)d_in[3];
    const float* si_W1  = (const float*)d_in[4];
    const float* si_W2  = (const float*)d_in[5];
    const float* rad_W1 = (const float*)d_in[6];
    const float* rad_b1 = (const float*)d_in[7];
    const float* rad_W2 = (const float*)d_in[8];
    const float* rad_b2 = (const float*)d_in[9];
    const float* rad_W3 = (const float*)d_in[10];
    const float* rad_b3 = (const float*)d_in[11];
    const float* pW1    = (const float*)d_in[12];
    const float* pb1    = (const float*)d_in[13];
    const float* pW2    = (const float*)d_in[14];
    const float* pb2    = (const float*)d_in[15];
    const float* pW3    = (const float*)d_in[16];
    const float* pb3    = (const float*)d_in[17];
    const float* out_W  = (const float*)d_in[18];
    const float* out_b  = (const float*)d_in[19];
    const float* ln_g   = (const float*)d_in[20];
    const float* ln_b   = (const float*)d_in[21];
    const int* ei       = (const int*)d_in[22];
    const int* batch    = (const int*)d_in[23];
    float* out = (float*)d_out;

    // capture slot = launch index 3 → k_msg(l=0)
    k_setup<<<SB_TOTAL, 256>>>(pos, ei, rad_W3, rad_b3, x, emb_W);           // 0

    for (int l = 0; l < LL; l++) {
        int cur = l & 1;
        k_radial<<<EE / 4, 256>>>(rad_W1 + l * 8 * 64, rad_b1 + l * 64,
                                  rad_W2 + l * 64 * 64, rad_b2 + l * 64);    // 1 (l=0)
        for (int c = 0; c < NCHUNK; c++) {
            k_gemm_h<<<dim3(27, EC / 128), 256>>>(c, l);                     // 2 (l=0)
            k_msg<<<EC / 16, 256>>>(cur, c * EC, ei);                        // 3 (l=0)
        }
        k_si<<<NN, 128>>>(cur, si_W0 + l * 32 * 32, si_W1 + l * 16 * 16, si_W2 + l * 8 * 8);
    }

    k_attmlp<<<NN / 8, 128>>>(pW1, pb1, pW2, pb2, pW3, pb3);
    k_pool<<<BBATCH, 256>>>(batch);
    k_out<<<BBATCH, 512>>>(out_W, out_b, ln_g, ln_b, out);
}

// round 17
// speedup vs baseline: 1.3193x; 1.3193x over previous
#include <cuda_runtime.h>
#include <cuda_fp16.h>
#include <math.h>
#include <stdint.h>

#define NN 4096
#define EE 32768
#define EC 8192
#define NCHUNK (EE / EC)
#define BBATCH 16
#define LL 4

#define SQ3C     1.73205080757f
#define SQ5C     2.23606797750f
#define INV_SQ3  0.57735026919f
#define INV_SQ5  0.44721359550f
#define INV_SQ75 0.36514837167f
#define A0C      0.13363062095f
#define A1C      0.20412414523f
#define A2C      0.27950849719f
#define ISQ32    0.17677669530f
#define ISQ16    0.25f
#define ISQ8     0.35355339059f
#define RBFN     0.79788458f

#define SB_GEOM 128
#define SB_PREP (SB_GEOM + 3456)
#define SB_NODE (SB_PREP + NN)
#define SB_TOTAL (SB_NODE + 1)

__constant__ float cQ[5][9] = {
    {0.f, 0.f, 0.86602540378f,  0.f, 0.f, 0.f,  0.86602540378f, 0.f, 0.f},
    {0.f, 0.86602540378f, 0.f,  0.86602540378f, 0.f, 0.f,  0.f, 0.f, 0.f},
    {-0.5f, 0.f, 0.f,  0.f, 1.f, 0.f,  0.f, 0.f, -0.5f},
    {0.f, 0.f, 0.f,  0.f, 0.f, 0.86602540378f,  0.f, 0.86602540378f, 0.f},
    {-0.86602540378f, 0.f, 0.f,  0.f, 0.f, 0.f,  0.f, 0.f, 0.86602540378f}};

__constant__ int segOff[12] = {0, 1024, 1536, 1792, 2304, 2560, 2816, 2944, 3200, 3328, 3392, 3456};
__constant__ int segU[11]   = {32, 16, 8, 32, 16, 16, 8, 32, 16, 8, 8};
__constant__ int segV[11]   = {32, 32, 32, 16, 16, 16, 16, 8, 8, 8, 8};

__device__ float  g_s1[EE * 3];
__device__ float  g_s2[EE * 5];
__device__ float  g_rbf[EE * 8];
__device__ __half g_hidh[EE * 64];
__device__ __half g_w3h[(size_t)LL * 64 * 3456];
__device__ float  g_b3p[LL * 3456];
__device__ __half g_wh[(size_t)EC * 3456];
__device__ float  g_h0[2][NN * 32];
__device__ float  g_h1[2][NN * 48];
__device__ float  g_h2[2][NN * 40];
__device__ float  g_agg0[NN * 32];
__device__ float  g_agg1[NN * 48];
__device__ float  g_agg2[NN * 40];
__device__ float  g_att[NN];
__device__ float  g_pool[BBATCH * 32];
__device__ float  g_C222[125];

__device__ __forceinline__ float siluf(float x) { return x / (1.f + expf(-x)); }

#define LDSM_X4(r0, r1, r2, r3, addr)                                              \
    asm volatile("ldmatrix.sync.aligned.m8n8.x4.shared.b16 {%0,%1,%2,%3}, [%4];"   \
                 : "=r"(r0), "=r"(r1), "=r"(r2), "=r"(r3) : "r"(addr))
#define LDSM_X4_T(r0, r1, r2, r3, addr)                                                 \
    asm volatile("ldmatrix.sync.aligned.m8n8.x4.trans.shared.b16 {%0,%1,%2,%3}, [%4];"  \
                 : "=r"(r0), "=r"(r1), "=r"(r2), "=r"(r3) : "r"(addr))
#define MMA_F16(d, a, b0, b1)                                                      \
    asm volatile("mma.sync.aligned.m16n8k16.row.col.f32.f16.f16.f32 "              \
                 "{%0,%1,%2,%3}, {%4,%5,%6,%7}, {%8,%9}, {%0,%1,%2,%3};"           \
                 : "+f"(d[0]), "+f"(d[1]), "+f"(d[2]), "+f"(d[3])                  \
                 : "r"(a[0]), "r"(a[1]), "r"(a[2]), "r"(a[3]), "r"(b0), "r"(b1))

// ---------------- fused setup — unchanged R15 ----------------
__global__ void k_setup(const float* __restrict__ pos, const int* __restrict__ ei,
                        const float* __restrict__ W3, const float* __restrict__ b3,
                        const float* __restrict__ x, const float* __restrict__ embW) {
    int b = blockIdx.x, t = threadIdx.x;
    if (b < SB_GEOM) {
        int e = b * 256 + t;
        int s = ei[e], d = ei[EE + e];
        float rx = pos[d * 3 + 0] - pos[s * 3 + 0];
        float ry = pos[d * 3 + 1] - pos[s * 3 + 1];
        float rz = pos[d * 3 + 2] - pos[s * 3 + 2];
        float dist = sqrtf(rx * rx + ry * ry + rz * rz);
        dist = fmaxf(dist, 1e-6f);
        float nx = rx / dist, ny = ry / dist, nz = rz / dist;
        g_s1[e * 3 + 0] = SQ3C * nx;
        g_s1[e * 3 + 1] = SQ3C * ny;
        g_s1[e * 3 + 2] = SQ3C * nz;
        g_s2[e * 5 + 0] = SQ5C * (SQ3C * nx * nz);
        g_s2[e * 5 + 1] = SQ5C * (SQ3C * nx * ny);
        g_s2[e * 5 + 2] = SQ5C * (ny * ny - 0.5f * (nx * nx + nz * nz));
        g_s2[e * 5 + 3] = SQ5C * (SQ3C * ny * nz);
        g_s2[e * 5 + 4] = SQ5C * (0.5f * SQ3C * (nz * nz - nx * nx));
#pragma unroll
        for (int i = 0; i < 8; i++) {
            float c = 6.f * (float)i / 7.f;
            float tt = dist - c;
            g_rbf[e * 8 + i] = expf(-2.f * tt * tt) * RBFN;
        }
    } else if (b < SB_PREP) {
        int idx = (b - SB_GEOM) * 256 + t;
        int l = idx / (64 * 3456);
        int rem = idx % (64 * 3456);
        int k = rem / 3456;
        int cp = rem % 3456;
        int seg = 0;
        while (cp >= segOff[seg + 1]) seg++;
        int local = cp - segOff[seg];
        int U = segU[seg], V = segV[seg];
        int v = local / U, u = local % U;
        int c = segOff[seg] + u * V + v;
        g_w3h[idx] = __float2half(W3[(size_t)l * 221184 + (size_t)k * 3456 + c]);
        if (k == 0) g_b3p[l * 3456 + cp] = b3[l * 3456 + c];
    } else if (b < SB_NODE) {
        int n = b - SB_PREP;
        __shared__ float xr[64];
        if (t < 64) xr[t] = x[n * 64 + t];
        __syncthreads();
        if (t < 32) {
            float s = 0.f;
#pragma unroll 8
            for (int c = 0; c < 64; c++) s += xr[c] * embW[c * 32 + t];
            g_h0[0][n * 32 + t] = s * 0.125f;
            g_agg0[n * 32 + t] = 0.f;
        }
        if (t < 48) { g_h1[0][n * 48 + t] = 0.f; g_agg1[n * 48 + t] = 0.f; }
        if (t < 40) { g_h2[0][n * 40 + t] = 0.f; g_agg2[n * 40 + t] = 0.f; }
    } else {
        __shared__ float T[256];
        __shared__ float red[256];
        float v = 0.f;
        if (t < 125) {
            int i = t / 25, j = (t / 5) % 5, k = t % 5;
            for (int a = 0; a < 3; a++)
                for (int bb = 0; bb < 3; bb++)
                    for (int c = 0; c < 3; c++)
                        v += cQ[i][a * 3 + bb] * cQ[j][bb * 3 + c] * cQ[k][c * 3 + a];
        }
        T[t] = v;
        red[t] = v * v;
        __syncthreads();
        for (int s = 128; s > 0; s >>= 1) {
            if (t < s) red[t] += red[t + s];
            __syncthreads();
        }
        float inv = rsqrtf(red[0]);
        if (t < 125) g_C222[t] = T[t] * inv;
    }
}

// ---------------- radial MLP — unchanged R15 ----------------
__global__ void k_radial(const float* __restrict__ W1, const float* __restrict__ b1,
                         const float* __restrict__ W2, const float* __restrict__ b2) {
    int le = threadIdx.x >> 6;
    int t = threadIdx.x & 63;
    int e = blockIdx.x * 4 + le;
    __shared__ __align__(16) float sh[4][64];
    const float* r = g_rbf + e * 8;
    float z = b1[t];
#pragma unroll
    for (int i = 0; i < 8; i++) z += r[i] * W1[i * 64 + t];
    sh[le][t] = siluf(z);
    __syncthreads();
    float z2 = b2[t];
    const float4* s4 = (const float4*)sh[le];
#pragma unroll
    for (int i = 0; i < 16; i++) {
        float4 a = s4[i];
        z2 += a.x * W2[(i * 4 + 0) * 64 + t];
        z2 += a.y * W2[(i * 4 + 1) * 64 + t];
        z2 += a.z * W2[(i * 4 + 2) * 64 + t];
        z2 += a.w * W2[(i * 4 + 3) * 64 + t];
    }
    g_hidh[e * 64 + t] = __float2half(siluf(z2));
}

// ---------------- fp16 GEMM: 128x128 tile — unchanged R15 (no occ attribute) ----------------
__global__ void __launch_bounds__(256) k_gemm_h(int chunk, int l) {
    __shared__ __align__(16) __half As[128 * 64];
    __shared__ __align__(16) __half Bs[64 * 128];
    int bx = blockIdx.x, by = blockIdx.y;
    int tid = threadIdx.x;
    const __half* Bm = g_w3h + (size_t)l * 221184;
    const float* bias = g_b3p + l * 3456;

    {
        int row = tid >> 1;
        int cq0 = (tid & 1) * 4;
        const uint4* src = (const uint4*)(g_hidh + (size_t)(chunk * EC + by * 128 + row) * 64);
#pragma unroll
        for (int q = 0; q < 4; q++) {
            int ck = cq0 + q;
            *(uint4*)&As[row * 64 + ((ck ^ (row & 7)) * 8)] = src[ck];
        }
    }
    {
        int k = tid >> 2;
        int bq0 = (tid & 3) * 4;
        const uint4* src = (const uint4*)(Bm + (size_t)k * 3456 + bx * 128);
#pragma unroll
        for (int q = 0; q < 4; q++) {
            int ck = bq0 + q;
            *(uint4*)&Bs[k * 128 + ((ck ^ (k & 7)) * 8)] = src[ck];
        }
    }
    __syncthreads();

    int lane = tid & 31, w = tid >> 5;
    int wr = w & 3, wc = w >> 2;
    int off = lane & 7, qd = lane >> 3;
    int rowSel = ((qd & 1) << 3) + off;
    int chkSel = qd >> 1;

    uint32_t aBase = (uint32_t)__cvta_generic_to_shared(As);
    uint32_t bBase = (uint32_t)__cvta_generic_to_shared(Bs);

    float acc[2][8][4];
#pragma unroll
    for (int mi = 0; mi < 2; mi++)
#pragma unroll
        for (int n8 = 0; n8 < 8; n8++)
#pragma unroll
            for (int q = 0; q < 4; q++) acc[mi][n8][q] = 0.f;

#pragma unroll
    for (int kk = 0; kk < 4; kk++) {
        uint32_t a[2][4];
#pragma unroll
        for (int mi = 0; mi < 2; mi++) {
            int row = wr * 32 + mi * 16 + rowSel;
            int chk = kk * 2 + chkSel;
            uint32_t ad = aBase + (uint32_t)(row * 64 + ((chk ^ (row & 7)) * 8)) * 2;
            LDSM_X4(a[mi][0], a[mi][1], a[mi][2], a[mi][3], ad);
        }
        int krow = kk * 16 + rowSel;
        int ksw = krow & 7;
        uint32_t b[4][4];
#pragma unroll
        for (int j = 0; j < 4; j++) {
            int chk = wc * 8 + j * 2 + chkSel;
            uint32_t bd = bBase + (uint32_t)(krow * 128 + ((chk ^ ksw) * 8)) * 2;
            LDSM_X4_T(b[j][0], b[j][1], b[j][2], b[j][3], bd);
        }
#pragma unroll
        for (int mi = 0; mi < 2; mi++)
#pragma unroll
            for (int j = 0; j < 4; j++) {
                MMA_F16(acc[mi][j * 2 + 0], a[mi], b[j][0], b[j][1]);
                MMA_F16(acc[mi][j * 2 + 1], a[mi], b[j][2], b[j][3]);
            }
    }

    int g = lane >> 2, t4 = lane & 3;
#pragma unroll
    for (int n8 = 0; n8 < 8; n8++) {
        int c = bx * 128 + wc * 64 + n8 * 8 + 2 * t4;
        float2 bv = *(const float2*)(bias + c);
#pragma unroll
        for (int mi = 0; mi < 2; mi++) {
            int r = by * 128 + wr * 32 + mi * 16 + g;
            *(__half2*)(g_wh + (size_t)r * 3456 + c) =
                __floats2half2_rn(acc[mi][n8][0] + bv.x, acc[mi][n8][1] + bv.y);
            *(__half2*)(g_wh + (size_t)(r + 8) * 3456 + c) =
                __floats2half2_rn(acc[mi][n8][2] + bv.x, acc[mi][n8][3] + bv.y);
        }
    }
}

// ---------------- message kernel: 64-thread blocks (2 warps, 4 edges) ----------------
__global__ void __launch_bounds__(64) k_msg(int cur, int e0, const int* __restrict__ ei) {
    __shared__ float S[4][400];
    int wid = threadIdx.x >> 5, lane = threadIdx.x & 31;
    int eA = e0 + (blockIdx.x * 2 + wid) * 2;
    int eB = eA + 1;
    float* PA = S[wid * 2];
    float* PB = S[wid * 2 + 1];
    int srcA = ei[eA], dstA = ei[EE + eA];
    int srcB = ei[eB], dstB = ei[EE + eB];
    const float* h0 = g_h0[cur];
    const float* h1 = g_h1[cur];
    const float* h2 = g_h2[cur];
    const __half* wpA = g_wh + (size_t)(eA - e0) * 3456;
    const __half* wpB = g_wh + (size_t)(eB - e0) * 3456;

#pragma unroll
    for (int h = 0; h < 2; h++) {
        float* P = h ? PB : PA;
        int e = h ? eB : eA;
        int src = h ? srcB : srcA;

        P[lane] = h0[src * 32 + lane];
        for (int i = lane; i < 48; i += 32) P[32 + i] = h1[src * 48 + i];
        for (int i = lane; i < 40; i += 32) P[80 + i] = h2[src * 40 + i];
        if (lane < 3) P[336 + lane] = g_s1[e * 3 + lane];
        if (lane < 5) P[339 + lane] = g_s2[e * 5 + lane];
        __syncwarp();

        if (lane < 9) {
            int i = lane / 3, j = lane % 3;
            float s = 0.f;
#pragma unroll
            for (int k = 0; k < 5; k++) s += P[339 + k] * cQ[k][i * 3 + j];
            P[344 + lane] = s;
        } else if (lane < 24) {
            int idx = lane - 9;
            int a = idx / 3, c = idx % 3;
            float s = 0.f;
#pragma unroll
            for (int b = 0; b < 3; b++) s += cQ[a][b * 3 + c] * P[336 + b];
            P[353 + idx] = s;
        } else {
            int u = lane - 24;
            float s = 0.f;
#pragma unroll
            for (int k = 0; k < 5; k++) s += P[80 + u * 5 + k] * P[339 + k];
            P[136 + u] = s * INV_SQ5;
        }
        __syncwarp();
        if (lane < 25) {
            int a = lane / 5, k = lane % 5;
            float s = 0.f;
#pragma unroll
            for (int b = 0; b < 5; b++) s += P[339 + b] * g_C222[(a * 5 + b) * 5 + k];
            P[368 + lane] = s;
        } else {
            int u = lane - 25;
            float s = 0.f;
#pragma unroll
            for (int i = 0; i < 3; i++) s += P[32 + u * 3 + i] * P[336 + i];
            P[120 + u] = s * INV_SQ3;
        }
        __syncwarp();
        if (lane < 9) {
            int u = lane + 7;
            float s = 0.f;
#pragma unroll
            for (int i = 0; i < 3; i++) s += P[32 + u * 3 + i] * P[336 + i];
            P[120 + u] = s * INV_SQ3;
        }
        __syncwarp();

        for (int idx = lane; idx < 192; idx += 32) {
            if (idx < 48) {
                int u = idx / 3, j = idx % 3;
                float s = 0.f;
#pragma unroll
                for (int i = 0; i < 3; i++) s += P[32 + u * 3 + i] * P[344 + i * 3 + j];
                P[144 + idx] = s * INV_SQ75;
            } else if (idx < 72) {
                int t = idx - 48;
                int u = t / 3, c = t % 3;
                float s = 0.f;
#pragma unroll
                for (int a = 0; a < 5; a++) s += P[80 + u * 5 + a] * P[353 + a * 3 + c];
                P[192 + t] = s * INV_SQ75;
            } else if (idx < 152) {
                int t = idx - 72;
                int u = t / 5, k = t % 5;
                float s = 0.f;
#pragma unroll
                for (int i = 0; i < 3; i++) s += P[32 + u * 3 + i] * P[353 + k * 3 + i];
                P[216 + t] = s * INV_SQ75;
            } else {
                int t = idx - 152;
                int u = t / 5, k = t % 5;
                float s = 0.f;
#pragma unroll
                for (int a = 0; a < 5; a++) s += P[80 + u * 5 + a] * P[368 + a * 5 + k];
                P[296 + t] = s;
            }
        }
        __syncwarp();
    }

#pragma unroll
    for (int h = 0; h < 2; h++) {
        float* P = h ? PB : PA;
        const __half* wp = h ? wpB : wpA;
        int dst = h ? dstB : dstA;
        int v = lane;
        float acc = 0.f;
        const uint4* q0 = (const uint4*)(wp + v * 32);
#pragma unroll
        for (int b = 0; b < 4; b++) {
            uint4 x = q0[b];
            const __half2* hh = (const __half2*)&x;
#pragma unroll
            for (int i = 0; i < 4; i++) {
                float2 f = __half22float2(hh[i]);
                int u = b * 8 + i * 2;
                acc += f.x * P[u] + f.y * P[u + 1];
            }
        }
        const uint4* q1 = (const uint4*)(wp + 1024 + v * 16);
#pragma unroll
        for (int b = 0; b < 2; b++) {
            uint4 x = q1[b];
            const __half2* hh = (const __half2*)&x;
#pragma unroll
            for (int i = 0; i < 4; i++) {
                float2 f = __half22float2(hh[i]);
                int u = b * 8 + i * 2;
                acc += f.x * P[120 + u] + f.y * P[120 + u + 1];
            }
        }
        {
            uint4 x = *(const uint4*)(wp + 1536 + v * 8);
            const __half2* hh = (const __half2*)&x;
#pragma unroll
            for (int i = 0; i < 4; i++) {
                float2 f = __half22float2(hh[i]);
                int u = i * 2;
                acc += f.x * P[136 + u] + f.y * P[136 + u + 1];
            }
        }
        atomicAdd(&g_agg0[dst * 32 + v], A0C * acc);
    }

    {
        int h = lane >> 4;
        int v = lane & 15;
        float* P = h ? PB : PA;
        const __half* wp = h ? wpB : wpA;
        int dst = h ? dstB : dstA;

        float p011 = 0.f;
        const uint4* q0 = (const uint4*)(wp + 1792 + v * 32);
#pragma unroll
        for (int b = 0; b < 4; b++) {
            uint4 x = q0[b];
            const __half2* hh = (const __half2*)&x;
#pragma unroll
            for (int i = 0; i < 4; i++) {
                float2 f = __half22float2(hh[i]);
                int u = b * 8 + i * 2;
                p011 += f.x * P[u] + f.y * P[u + 1];
            }
        }
        float a1c[3] = {0.f, 0.f, 0.f};
        float b1c[3] = {0.f, 0.f, 0.f};
        const uint4* qa = (const uint4*)(wp + 2304 + v * 16);
#pragma unroll
        for (int b = 0; b < 2; b++) {
            uint4 x = qa[b];
            const __half2* hh = (const __half2*)&x;
#pragma unroll
            for (int i = 0; i < 4; i++) {
                float2 f = __half22float2(hh[i]);
                int u = b * 8 + i * 2;
#pragma unroll
                for (int j = 0; j < 3; j++)
                    a1c[j] += f.x * P[32 + u * 3 + j] + f.y * P[32 + (u + 1) * 3 + j];
            }
        }
        const uint4* qb = (const uint4*)(wp + 2560 + v * 16);
#pragma unroll
        for (int b = 0; b < 2; b++) {
            uint4 x = qb[b];
            const __half2* hh = (const __half2*)&x;
#pragma unroll
            for (int i = 0; i < 4; i++) {
                float2 f = __half22float2(hh[i]);
                int u = b * 8 + i * 2;
#pragma unroll
                for (int j = 0; j < 3; j++)
                    b1c[j] += f.x * P[144 + u * 3 + j] + f.y * P[144 + (u + 1) * 3 + j];
            }
        }
        {
            uint4 x = *(const uint4*)(wp + 2816 + v * 8);
            const __half2* hh = (const __half2*)&x;
#pragma unroll
            for (int i = 0; i < 4; i++) {
                float2 f = __half22float2(hh[i]);
                int u = i * 2;
#pragma unroll
                for (int j = 0; j < 3; j++)
                    b1c[j] += f.x * P[192 + u * 3 + j] + f.y * P[192 + (u + 1) * 3 + j];
            }
        }
#pragma unroll
        for (int j = 0; j < 3; j++) {
            float m = A1C * ((p011 * P[336 + j] + a1c[j]) * INV_SQ3 + b1c[j]);
            atomicAdd(&g_agg1[dst * 48 + v * 3 + j], m);
        }
    }

    if (lane < 16) {
        int h = lane >> 3;
        int v = lane & 7;
        float* P = h ? PB : PA;
        const __half* wp = h ? wpB : wpA;
        int dst = h ? dstB : dstA;

        float p022 = 0.f;
        const uint4* q0 = (const uint4*)(wp + 2944 + v * 32);
#pragma unroll
        for (int b = 0; b < 4; b++) {
            uint4 x = q0[b];
            const __half2* hh = (const __half2*)&x;
#pragma unroll
            for (int i = 0; i < 4; i++) {
                float2 f = __half22float2(hh[i]);
                int u = b * 8 + i * 2;
                p022 += f.x * P[u] + f.y * P[u + 1];
            }
        }
        float t2c[5] = {0.f, 0.f, 0.f, 0.f, 0.f};
        const uint4* qa = (const uint4*)(wp + 3200 + v * 16);
#pragma unroll
        for (int b = 0; b < 2; b++) {
            uint4 x = qa[b];
            const __half2* hh = (const __half2*)&x;
#pragma unroll
            for (int i = 0; i < 4; i++) {
                float2 f = __half22float2(hh[i]);
                int u = b * 8 + i * 2;
#pragma unroll
                for (int k = 0; k < 5; k++)
                    t2c[k] += f.x * P[216 + u * 5 + k] + f.y * P[216 + (u + 1) * 5 + k];
            }
        }
        {
            uint4 x = *(const uint4*)(wp + 3328 + v * 8);
            const __half2* hh = (const __half2*)&x;
#pragma unroll
            for (int i = 0; i < 4; i++) {
                float2 f = __half22float2(hh[i]);
                int u = i * 2;
#pragma unroll
                for (int k = 0; k < 5; k++)
                    t2c[k] += (f.x * P[80 + u * 5 + k] + f.y * P[80 + (u + 1) * 5 + k]) * INV_SQ5;
            }
        }
        {
            uint4 x = *(const uint4*)(wp + 3392 + v * 8);
            const __half2* hh = (const __half2*)&x;
#pragma unroll
            for (int i = 0; i < 4; i++) {
                float2 f = __half22float2(hh[i]);
                int u = i * 2;
#pragma unroll
                for (int k = 0; k < 5; k++)
                    t2c[k] += f.x * P[296 + u * 5 + k] + f.y * P[296 + (u + 1) * 5 + k];
            }
        }
#pragma unroll
        for (int k = 0; k < 5; k++) {
            float m = A2C * (p022 * P[339 + k] * INV_SQ5 + t2c[k]);
            atomicAdd(&g_agg2[dst * 40 + v * 5 + k], m);
        }
    }
}

// ---------------- self interaction — unchanged ----------------
__global__ void k_si(int cur, const float* __restrict__ siW0, const float* __restrict__ siW1,
                     const float* __restrict__ siW2) {
    int n = blockIdx.x, t = threadIdx.x;
    int nxt = cur ^ 1;
    __shared__ float o0[32], o1[48], o2[40];
    if (t < 32) o0[t] = g_h0[cur][n * 32 + t];
    else if (t < 80) o1[t - 32] = g_h1[cur][n * 48 + (t - 32)];
    else if (t < 120) o2[t - 80] = g_h2[cur][n * 40 + (t - 80)];
    __syncthreads();
    if (t < 32) {
        float s = 0.f;
#pragma unroll 8
        for (int u = 0; u < 32; u++) s += o0[u] * siW0[u * 32 + t];
        g_h0[nxt][n * 32 + t] = s * ISQ32 + g_agg0[n * 32 + t];
        g_agg0[n * 32 + t] = 0.f;
    } else if (t < 80) {
        int idx = t - 32;
        int v = idx / 3, i = idx % 3;
        float s = 0.f;
#pragma unroll 4
        for (int u = 0; u < 16; u++) s += o1[u * 3 + i] * siW1[u * 16 + v];
        g_h1[nxt][n * 48 + idx] = s * ISQ16 + g_agg1[n * 48 + idx];
        g_agg1[n * 48 + idx] = 0.f;
    } else if (t < 120) {
        int idx = t - 80;
        int v = idx / 5, k = idx % 5;
        float s = 0.f;
#pragma unroll
        for (int u = 0; u < 8; u++) s += o2[u * 5 + k] * siW2[u * 8 + v];
        g_h2[nxt][n * 40 + idx] = s * ISQ8 + g_agg2[n * 40 + idx];
        g_agg2[n * 40 + idx] = 0.f;
    }
}

// ---------------- attention MLP — unchanged ----------------
__global__ void k_attmlp(const float* __restrict__ W1, const float* __restrict__ b1,
                         const float* __restrict__ W2, const float* __restrict__ b2,
                         const float* __restrict__ W3, const float* __restrict__ b3) {
    int n0 = blockIdx.x * 8;
    int t = threadIdx.x;
    __shared__ float hr[8][32];
    __shared__ float a1[8][128];
    __shared__ float red[128];
    for (int i = t; i < 256; i += 128)
        hr[i >> 5][i & 31] = g_h0[0][(n0 + (i >> 5)) * 32 + (i & 31)];
    __syncthreads();
    float z[8];
    float bb = b1[t];
#pragma unroll
    for (int n = 0; n < 8; n++) z[n] = bb;
    for (int c = 0; c < 32; c++) {
        float wv = W1[c * 128 + t];
#pragma unroll
        for (int n = 0; n < 8; n++) z[n] += hr[n][c] * wv;
    }
#pragma unroll
    for (int n = 0; n < 8; n++) a1[n][t] = siluf(z[n]);
    __syncthreads();
    float z2[8];
    float bb2 = b2[t];
#pragma unroll
    for (int n = 0; n < 8; n++) z2[n] = bb2;
    for (int c = 0; c < 128; c++) {
        float wv = W2[c * 128 + t];
#pragma unroll
        for (int n = 0; n < 8; n++) z2[n] += a1[n][c] * wv;
    }
    float w3 = W3[t];
    float b3v = b3[0];
    for (int n = 0; n < 8; n++) {
        red[t] = siluf(z2[n]) * w3;
        __syncthreads();
        for (int s = 64; s > 0; s >>= 1) {
            if (t < s) red[t] += red[t + s];
            __syncthreads();
        }
        if (t == 0) g_att[n0 + n] = red[0] + b3v;
        __syncthreads();
    }
}

// ---------------- pooling — unchanged ----------------
__global__ void k_pool(const int* __restrict__ batch) {
    int b = blockIdx.x, tid = threadIdx.x;
    int lane = tid & 31;
    __shared__ float red[256];
    __shared__ float gacc[32];
    __shared__ float s_amax, s_den;
    float lm = -1e30f;
    for (int n = tid; n < NN; n += 256)
        if (batch[n] == b) lm = fmaxf(lm, g_att[n]);
    red[tid] = lm;
    __syncthreads();
    for (int s = 128; s > 0; s >>= 1) {
        if (tid < s) red[tid] = fmaxf(red[tid], red[tid + s]);
        __syncthreads();
    }
    if (tid == 0) s_amax = red[0];
    if (tid < 32) gacc[tid] = 0.f;
    __syncthreads();
    float amax = s_amax;
    float lden = 0.f;
    float acc[32];
#pragma unroll
    for (int c = 0; c < 32; c++) acc[c] = 0.f;
    for (int n = tid; n < NN; n += 256)
        if (batch[n] == b) {
            float ex = expf(g_att[n] - amax);
            lden += ex;
#pragma unroll
            for (int c = 0; c < 32; c++) acc[c] += ex * g_h0[0][n * 32 + c];
        }
#pragma unroll
    for (int c = 0; c < 32; c++) {
        float v = acc[c];
#pragma unroll
        for (int o = 16; o > 0; o >>= 1) v += __shfl_xor_sync(0xffffffff, v, o);
        if (lane == 0) atomicAdd(&gacc[c], v);
    }
    red[tid] = lden;
    __syncthreads();
    for (int s = 128; s > 0; s >>= 1) {
        if (tid < s) red[tid] += red[tid + s];
        __syncthreads();
    }
    if (tid == 0) s_den = red[0];
    __syncthreads();
    if (tid < 32) g_pool[b * 32 + tid] = gacc[tid] / s_den;
}

// ---------------- final linear + layernorm — unchanged ----------------
__global__ void k_out(const float* __restrict__ W, const float* __restrict__ bo,
                      const float* __restrict__ lg, const float* __restrict__ lb,
                      float* __restrict__ out) {
    int b = blockIdx.x, j = threadIdx.x;
    __shared__ float gr[32];
    __shared__ float red[512];
    if (j < 32) gr[j] = g_pool[b * 32 + j];
    __syncthreads();
    float o = bo[j];
#pragma unroll 8
    for (int c = 0; c < 32; c++) o += gr[c] * W[c * 512 + j];
    red[j] = o;
    __syncthreads();
    for (int s = 256; s > 0; s >>= 1) {
        if (j < s) red[j] += red[j + s];
        __syncthreads();
    }
    float mu = red[0] / 512.f;
    __syncthreads();
    float d = o - mu;
    red[j] = d * d;
    __syncthreads();
    for (int s = 256; s > 0; s >>= 1) {
        if (j < s) red[j] += red[j + s];
        __syncthreads();
    }
    float var = red[0] / 512.f;
    out[b * 512 + j] = d * rsqrtf(var + 1e-5f) * lg[j] + lb[j];
}

extern "C" void kernel_launch(void* const* d_in, const int* in_sizes, int n_in,
                              void* d_out, int out_size) {
    const float* x      = (const float*)d_in[0];
    const float* pos    = (const float*)d_in[1];
    const float* emb_W  = (const float*)d_in[2];
    const float* si_W0  = (const float*)d_in[3];
    const float* si_W1  = (const float*)d_in[4];
    const float* si_W2  = (const float*)d_in[5];
    const float* rad_W1 = (const float*)d_in[6];
    const float* rad_b1 = (const float*)d_in[7];
    const float* rad_W2 = (const float*)d_in[8];
    const float* rad_b2 = (const float*)d_in[9];
    const float* rad_W3 = (const float*)d_in[10];
    const float* rad_b3 = (const float*)d_in[11];
    const float* pW1    = (const float*)d_in[12];
    const float* pb1    = (const float*)d_in[13];
    const float* pW2    = (const float*)d_in[14];
    const float* pb2    = (const float*)d_in[15];
    const float* pW3    = (const float*)d_in[16];
    const float* pb3    = (const float*)d_in[17];
    const float* out_W  = (const float*)d_in[18];
    const float* out_b  = (const float*)d_in[19];
    const float* ln_g   = (const float*)d_in[20];
    const float* ln_b   = (const float*)d_in[21];
    const int* ei       = (const int*)d_in[22];
    const int* batch    = (const int*)d_in[23];
    float* out = (float*)d_out;

    // capture slot = launch index 3 → k_msg(l=0, c=0)
    k_setup<<<SB_TOTAL, 256>>>(pos, ei, rad_W3, rad_b3, x, emb_W);           // 0

    for (int l = 0; l < LL; l++) {
        int cur = l & 1;
        k_radial<<<EE / 4, 256>>>(rad_W1 + l * 8 * 64, rad_b1 + l * 64,
                                  rad_W2 + l * 64 * 64, rad_b2 + l * 64);    // 1 (l=0)
        for (int c = 0; c < NCHUNK; c++) {
            k_gemm_h<<<dim3(27, EC / 128), 256>>>(c, l);                     // 2 (l=0,c=0)
            k_msg<<<EC / 4, 64>>>(cur, c * EC, ei);                          // 3 (l=0,c=0)
        }
        k_si<<<NN, 128>>>(cur, si_W0 + l * 32 * 32, si_W1 + l * 16 * 16, si_W2 + l * 8 * 8);
    }

    k_attmlp<<<NN / 8, 128>>>(pW1, pb1, pW2, pb2, pW3, pb3);
    k_pool<<<BBATCH, 256>>>(batch);
    k_out<<<BBATCH, 512>>>(out_W, out_b, ln_g, ln_b, out);
}